// round 7
// baseline (speedup 1.0000x reference)
#include <cuda_runtime.h>

#define NTAGS   1024
#define NCTA    64
#define TPB     512
#define WARPS   16           // warps per CTA; one E-row per warp
#define TSTEPS  65536
#define SPIN_CAP (1u << 24)  // watchdog: unreachable in normal operation

// Persistent device state.
// g_ab: {f32 alpha, u32 tag} packed in 8B -> one b64 load observes
//       value+readiness atomically (no fences needed anywhere).
// g_rep: one tag per producer CTA, contiguous (2 cache lines) -> cheap polling.
__device__ __align__(16) unsigned long long g_ab[2][NTAGS];
__device__ __align__(16) unsigned           g_rep[2][NCTA];
__device__ unsigned g_gen = 0;   // bumped once per launch (replay-safe tags)

__device__ __forceinline__ unsigned long long ld_rlx64(const unsigned long long* p) {
    unsigned long long v;
    asm volatile("ld.relaxed.gpu.global.b64 %0, [%1];" : "=l"(v) : "l"(p));
    return v;
}
__device__ __forceinline__ void st_rlx64(unsigned long long* p, unsigned long long v) {
    asm volatile("st.relaxed.gpu.global.b64 [%0], %1;" :: "l"(p), "l"(v) : "memory");
}
__device__ __forceinline__ unsigned ld_rlx32(const unsigned* p) {
    unsigned v;
    asm volatile("ld.relaxed.gpu.global.u32 %0, [%1];" : "=r"(v) : "l"(p));
    return v;
}
__device__ __forceinline__ void st_rlx32(unsigned* p, unsigned v) {
    asm volatile("st.relaxed.gpu.global.u32 [%0], %1;" :: "l"(p), "r"(v) : "memory");
}
__device__ __forceinline__ unsigned long long pack_av(float a, unsigned tag) {
    return ((unsigned long long)tag << 32) | (unsigned long long)__float_as_uint(a);
}
__device__ __forceinline__ float    val_of(unsigned long long q) { return __uint_as_float((unsigned)q); }
__device__ __forceinline__ unsigned tag_of(unsigned long long q) { return (unsigned)(q >> 32); }

__global__ void __launch_bounds__(TPB, 1)
crf_kernel(const float* __restrict__ unary,
           const float* __restrict__ trans,
           const int*   __restrict__ start_p,
           const int*   __restrict__ end_p,
           float*       __restrict__ out)
{
    const int tid  = threadIdx.x;
    const int lane = tid & 31;
    const int w    = tid >> 5;           // 16 warps
    const int cta  = blockIdx.x;
    const int row  = cta * WARPS + w;    // this warp's tag row

    __shared__ float sx[NTAGS];          // exp(alpha - m); single buffer is safe:
                                         // step-t reads precede next iteration's
                                         // first barrier; step-t+1 writes follow it.
    __shared__ float s_a[2][WARPS];      // this CTA's alpha rows, double-buffered
    __shared__ int   s_bail;             // watchdog flag

    const unsigned gen = g_gen;          // stream-ordered across graph replays
    // tag(step s) = gen*65536 + s + 1  (never 0, unique across replays)

    if (tid == 0) s_bail = 0;

    // ---- E row in registers: warp w owns row `row`, lane owns cols {lane+32k}
    float E[32];
    #pragma unroll
    for (int k = 0; k < 32; k++)
        E[k] = __expf(__ldg(&trans[(size_t)row * NTAGS + lane + 32 * k]));

    // ---- Step 0: alpha_0[i] = trans[i, start] + u_0[i] ------------------
    float u_next = 0.0f;                 // lane0-only: unary for the next step
    if (lane == 0) {
        const int sidx = *start_p;
        const float a0 = __ldg(&trans[(size_t)row * NTAGS + sidx]) + __ldg(&unary[row]);
        s_a[0][w] = a0;
        s_a[1][w] = a0;                  // stands in for alpha_{-1} at t=1,2
        st_rlx64(&g_ab[0][row], pack_av(a0, gen * 65536u + 1u));
        if (w == WARPS - 1) st_rlx32(&g_rep[0][cta], gen * 65536u + 1u);
        u_next = __ldcs(&unary[(size_t)NTAGS + row]);
    }
    __syncthreads();

    // ---- Main scan ------------------------------------------------------
    for (int t = 1; t < TSTEPS; t++) {
        const int pb = (t - 1) & 1;      // buffer holding alpha_{t-1}
        const int b  = t & 1;

        // exp-offset from alpha_{t-2} (race-free via double buffer + barriers).
        float mm = s_a[b][0];
        #pragma unroll
        for (int r = 1; r < WARPS; r++) mm = fmaxf(mm, s_a[b][r]);
        const float m = mm + 30.0f;      // covers 2 steps of drift + tag spread

        const unsigned want = gen * 65536u + (unsigned)t;  // tag of step t-1

        // NARROW poll: warp 0 spins on the 64 contiguous rep tags (2 lines).
        if (w == 0) {
            unsigned spins = 0;
            for (;;) {
                const unsigned r0 = ld_rlx32(&g_rep[pb][lane]);
                const unsigned r1 = ld_rlx32(&g_rep[pb][lane + 32]);
                const bool ok = ((r0 ^ want) | (r1 ^ want)) == 0u;
                if (__all_sync(0xffffffffu, ok)) break;
                if (++spins > SPIN_CAP) { s_bail = 1; break; }
            }
        }
        __syncthreads();                 // release consumers; bail broadcast point
        if (s_bail) break;

        // WIDE load exactly once, self-verifying (retries = rare stragglers).
        const unsigned long long* src = g_ab[pb];
        unsigned long long q0 = ld_rlx64(src + tid);
        unsigned long long q1 = ld_rlx64(src + tid + 512);
        {
            unsigned spins = 0;
            while (((tag_of(q0) ^ want) | (tag_of(q1) ^ want)) != 0u) {
                q0 = ld_rlx64(src + tid);
                q1 = ld_rlx64(src + tid + 512);
                if (++spins > SPIN_CAP) break;
            }
        }

        sx[tid]       = __expf(val_of(q0) - m);
        sx[tid + 512] = __expf(val_of(q1) - m);
        __syncthreads();

        // Row stage: warp w computes row `row` over all 1024 cols.
        float a0 = 0.f, a1 = 0.f, a2 = 0.f, a3 = 0.f;
        #pragma unroll
        for (int k = 0; k < 32; k += 4) {
            a0 = fmaf(E[k + 0], sx[lane + 32 * (k + 0)], a0);
            a1 = fmaf(E[k + 1], sx[lane + 32 * (k + 1)], a1);
            a2 = fmaf(E[k + 2], sx[lane + 32 * (k + 2)], a2);
            a3 = fmaf(E[k + 3], sx[lane + 32 * (k + 3)], a3);
        }
        float S = (a0 + a1) + (a2 + a3);
        #pragma unroll
        for (int msk = 16; msk >= 1; msk >>= 1)
            S += __shfl_xor_sync(0xffffffffu, S, msk);

        if (lane == 0) {
            const float alpha = __logf(S) + m + u_next;
            s_a[b][w] = alpha;
            st_rlx64(&g_ab[b][row], pack_av(alpha, want + 1u));
            if (w == WARPS - 1) st_rlx32(&g_rep[b][cta], want + 1u);
            const int tn = (t + 1 < TSTEPS) ? t + 1 : t;
            u_next = __ldcs(&unary[(size_t)tn * NTAGS + row]);
        }
        // no trailing barrier: next iteration's barriers provide ordering
    }

    // ---- Terminal logsumexp (CTA 0) -------------------------------------
    if (cta == 0) {
        const unsigned want = gen * 65536u + (unsigned)TSTEPS; // tag of step T-1
        const unsigned long long* src = g_ab[(TSTEPS - 1) & 1];
        unsigned long long q0 = ld_rlx64(src + tid);
        unsigned long long q1 = ld_rlx64(src + tid + 512);
        {
            unsigned spins = 0;
            while (((tag_of(q0) ^ want) | (tag_of(q1) ^ want)) != 0u) {
                q0 = ld_rlx64(src + tid);
                q1 = ld_rlx64(src + tid + 512);
                if (++spins > SPIN_CAP) break;
            }
        }

        const int eidx = *end_p;
        const float x0 = val_of(q0) + __ldg(&trans[(size_t)eidx * NTAGS + tid]);
        const float x1 = val_of(q1) + __ldg(&trans[(size_t)eidx * NTAGS + tid + 512]);

        float mx = fmaxf(x0, x1);
        #pragma unroll
        for (int msk = 16; msk >= 1; msk >>= 1)
            mx = fmaxf(mx, __shfl_xor_sync(0xffffffffu, mx, msk));
        if (lane == 0) sx[w] = mx;
        __syncthreads();
        float M = sx[0];
        #pragma unroll
        for (int w2 = 1; w2 < WARPS; w2++) M = fmaxf(M, sx[w2]);

        float s = __expf(x0 - M) + __expf(x1 - M);
        #pragma unroll
        for (int msk = 16; msk >= 1; msk >>= 1)
            s += __shfl_xor_sync(0xffffffffu, s, msk);
        if (lane == 0) sx[32 + w] = s;
        __syncthreads();

        if (tid == 0) {
            float Ssum = sx[32];
            #pragma unroll
            for (int w2 = 1; w2 < WARPS; w2++) Ssum += sx[32 + w2];
            out[0] = __logf(Ssum) + M;
            g_gen = gen + 1;             // version tags for the next replay
        }
    }
}

extern "C" void kernel_launch(void* const* d_in, const int* in_sizes, int n_in,
                              void* d_out, int out_size)
{
    const float* unary = (const float*)d_in[0];   // [65536, 1024] f32
    const float* trans = (const float*)d_in[1];   // [1024, 1024]  f32
    const int*   sidx  = (const int*)d_in[2];     // scalar
    const int*   eidx  = (const int*)d_in[3];     // scalar
    float*       out   = (float*)d_out;           // scalar f32

    crf_kernel<<<NCTA, TPB>>>(unary, trans, sidx, eidx, out);
}